// round 2
// baseline (speedup 1.0000x reference)
#include <cuda_runtime.h>
#include <cstdint>

#define NEG_PENALTY 0.03f
#define BATCH 64
#define NCLS  2048
#define LL    1024
#define NT    256

__global__ void zero_out_kernel(float* out) { out[0] = 0.0f; }

__global__ __launch_bounds__(NT)
void ranking_loss_kernel(const float* __restrict__ ranks,
                         const int*   __restrict__ labels,
                         const void*  __restrict__ ids_raw,
                         float* __restrict__ out)
{
    __shared__ float s_pos[LL];   // pos ranks, sorted ascending (padded +INF)
    __shared__ float s_neg[LL];   // neg ranks
    __shared__ float s_pre[LL];   // inclusive prefix sums of sorted pos
    __shared__ float s_tmp[LL];   // scan ping-pong
    __shared__ int   s_cnt[2];
    __shared__ float s_red[NT];

    const int b   = blockIdx.x;
    const int tid = threadIdx.x;

    // --- dtype sniff: int64 ids have zero high words at odd 32-bit indices ---
    const int* w32 = (const int*)ids_raw;
    const bool is64 = ((w32[201] | w32[401] | w32[601] | w32[801]) == 0);
    const long long* w64 = (const long long*)ids_raw;

    if (tid < 2) s_cnt[tid] = 0;
    __syncthreads();

    // ---- gather columns by class id and partition into pos / neg ----
    for (int l = tid; l < LL; l += NT) {
        int id = is64 ? (int)w64[l] : w32[l];
        float r  = ranks[b * NCLS + id];
        int lab  = labels[b * NCLS + id];
        if (lab == 1) { int p = atomicAdd(&s_cnt[0], 1); s_pos[p] = r; }
        else          { int p = atomicAdd(&s_cnt[1], 1); s_neg[p] = r; }
    }
    __syncthreads();

    const int np = s_cnt[0];
    const int nn = s_cnt[1];

    // pad pos with +INF so bitonic network sorts full power-of-2 size
    for (int l = np + tid; l < LL; l += NT) s_pos[l] = __int_as_float(0x7f800000);
    __syncthreads();

    // ---- bitonic sort s_pos ascending ----
    for (int k = 2; k <= LL; k <<= 1) {
        for (int j = k >> 1; j > 0; j >>= 1) {
            for (int i = tid; i < LL; i += NT) {
                int ixj = i ^ j;
                if (ixj > i) {
                    float a = s_pos[i];
                    float c = s_pos[ixj];
                    bool up = ((i & k) == 0);
                    if ((a > c) == up) { s_pos[i] = c; s_pos[ixj] = a; }
                }
            }
            __syncthreads();
        }
    }

    // ---- inclusive prefix sum of sorted pos (pads contribute 0) ----
    for (int i = tid; i < LL; i += NT) s_pre[i] = (i < np) ? s_pos[i] : 0.0f;
    __syncthreads();
    for (int s = 1; s < LL; s <<= 1) {
        for (int i = tid; i < LL; i += NT)
            s_tmp[i] = s_pre[i] + ((i >= s) ? s_pre[i - s] : 0.0f);
        __syncthreads();
        for (int i = tid; i < LL; i += NT) s_pre[i] = s_tmp[i];
        __syncthreads();
    }

    // ---- per neg value: closed-form contribution k*x - prefix(k) ----
    float acc = 0.0f;
    for (int ww = tid; ww < nn; ww += NT) {
        float x = s_neg[ww] + NEG_PENALTY;
        // k = count of sorted pos values strictly < x (ties contribute 0)
        int lo = 0, hi = np;
        while (lo < hi) {
            int mid = (lo + hi) >> 1;
            if (s_pos[mid] < x) lo = mid + 1; else hi = mid;
        }
        int k = lo;
        if (k > 0) acc += (float)k * x - s_pre[k - 1];
    }

    // ---- block reduce, one atomic per block ----
    s_red[tid] = acc;
    __syncthreads();
    for (int s = NT >> 1; s > 0; s >>= 1) {
        if (tid < s) s_red[tid] += s_red[tid + s];
        __syncthreads();
    }
    if (tid == 0) atomicAdd(out, s_red[0] * (1.0f / (float)BATCH));
}

extern "C" void kernel_launch(void* const* d_in, const int* in_sizes, int n_in,
                              void* d_out, int out_size)
{
    const float* ranks  = (const float*)d_in[0];   // [B, C] f32
    const int*   labels = (const int*)d_in[1];     // [B, C] i32
    const void*  ids    = d_in[2];                 // [L] i64 or i32 (sniffed)
    float* out = (float*)d_out;                    // [1] f32

    zero_out_kernel<<<1, 1>>>(out);
    ranking_loss_kernel<<<BATCH, NT>>>(ranks, labels, ids, out);
}

// round 3
// speedup vs baseline: 2.4956x; 2.4956x over previous
#include <cuda_runtime.h>

#define NEG_PENALTY 0.03f
#define BATCH 64
#define NCLS  2048
#define LL    1024
#define NT    1024
#define FULLM 0xffffffffu

__global__ void zero_out_kernel(float* out) { out[0] = 0.0f; }

__global__ __launch_bounds__(NT)
void ranking_loss_kernel(const float* __restrict__ ranks,
                         const int*   __restrict__ labels,
                         const void*  __restrict__ ids_raw,
                         float* __restrict__ out)
{
    __shared__ float s_pos[LL];    // sorted pos (padded +INF)
    __shared__ float s_neg[LL];    // neg ranks
    __shared__ float s_pre[LL];    // inclusive prefix sums of sorted pos
    __shared__ float s_warp[32];   // warp partials (scan / reduce)
    __shared__ int   s_cnt[2];

    const int b    = blockIdx.x;
    const int tid  = threadIdx.x;
    const int lane = tid & 31;
    const int wid  = tid >> 5;

    // --- dtype sniff: int64 ids have zero high words at odd 32-bit indices ---
    const int* w32 = (const int*)ids_raw;
    const bool is64 = ((w32[201] | w32[401] | w32[601] | w32[801]) == 0);
    const long long* w64 = (const long long*)ids_raw;

    if (tid < 2) s_cnt[tid] = 0;
    __syncthreads();

    // ---- gather + warp-aggregated partition into pos / neg ----
    {
        int   id  = is64 ? (int)w64[tid] : w32[tid];
        float r   = __ldg(&ranks[b * NCLS + id]);
        int   lab = __ldg(&labels[b * NCLS + id]);
        bool ispos = (lab == 1);
        unsigned m = __ballot_sync(FULLM, ispos);
        int npos_w  = __popc(m);
        int rank_lt = __popc(m & ((1u << lane) - 1u));
        int basep = 0, basen = 0;
        if (lane == 0) {
            basep = atomicAdd(&s_cnt[0], npos_w);
            basen = atomicAdd(&s_cnt[1], 32 - npos_w);
        }
        basep = __shfl_sync(FULLM, basep, 0);
        basen = __shfl_sync(FULLM, basen, 0);
        if (ispos) s_pos[basep + rank_lt]          = r;
        else       s_neg[basen + (lane - rank_lt)] = r;
    }
    __syncthreads();

    const int np = s_cnt[0];
    const int nn = s_cnt[1];

    // pad pos with +INF to full 1024
    if (tid >= np) s_pos[tid] = __int_as_float(0x7f800000);
    __syncthreads();

    // ================= bitonic sort, 1 element / thread =================
    // in-warp rounds k = 2..32 entirely via shuffles (zero barriers)
    float x = s_pos[tid];
    #pragma unroll
    for (int k = 2; k <= 32; k <<= 1) {
        #pragma unroll
        for (int j = k >> 1; j >= 1; j >>= 1) {
            float y = __shfl_xor_sync(FULLM, x, j);
            bool up      = ((tid & k) == 0);
            bool lowhalf = ((tid & j) == 0);
            x = (lowhalf == up) ? fminf(x, y) : fmaxf(x, y);
        }
    }
    s_pos[tid] = x;
    __syncthreads();

    // cross-warp rounds k = 64..1024: smem pair-stages for j>=32, shfl for j<32
    #pragma unroll
    for (int k = 64; k <= LL; k <<= 1) {
        for (int j = k >> 1; j >= 32; j >>= 1) {
            if (tid < LL / 2) {
                int p  = tid;
                int i  = ((p & ~(j - 1)) << 1) | (p & (j - 1));
                int ij = i | j;
                float a = s_pos[i];
                float c = s_pos[ij];
                bool up = ((i & k) == 0);
                if ((a > c) == up) { s_pos[i] = c; s_pos[ij] = a; }
            }
            __syncthreads();
        }
        x = s_pos[tid];
        #pragma unroll
        for (int j = 16; j >= 1; j >>= 1) {
            float y = __shfl_xor_sync(FULLM, x, j);
            bool up      = ((tid & k) == 0);
            bool lowhalf = ((tid & j) == 0);
            x = (lowhalf == up) ? fminf(x, y) : fmaxf(x, y);
        }
        s_pos[tid] = x;
        __syncthreads();
    }

    // ========== inclusive prefix sum of sorted pos (shuffle scan) ==========
    float v = (tid < np) ? s_pos[tid] : 0.0f;
    #pragma unroll
    for (int d = 1; d < 32; d <<= 1) {
        float t = __shfl_up_sync(FULLM, v, d);
        if (lane >= d) v += t;
    }
    if (lane == 31) s_warp[wid] = v;
    __syncthreads();
    if (wid == 0) {
        float wv = s_warp[lane];
        #pragma unroll
        for (int d = 1; d < 32; d <<= 1) {
            float t = __shfl_up_sync(FULLM, wv, d);
            if (lane >= d) wv += t;
        }
        s_warp[lane] = wv;
    }
    __syncthreads();
    float off = (wid > 0) ? s_warp[wid - 1] : 0.0f;
    s_pre[tid] = v + off;
    __syncthreads();

    // ====== per neg: closed-form contribution k*x - prefix(k) ======
    float acc = 0.0f;
    if (tid < nn) {
        float xq = s_neg[tid] + NEG_PENALTY;
        int lo = 0, hi = np;
        while (lo < hi) {
            int mid = (lo + hi) >> 1;
            if (s_pos[mid] < xq) lo = mid + 1; else hi = mid;
        }
        if (lo > 0) acc = (float)lo * xq - s_pre[lo - 1];
    }

    // ====== block reduce via shuffles, one atomic per block ======
    #pragma unroll
    for (int d = 16; d >= 1; d >>= 1)
        acc += __shfl_down_sync(FULLM, acc, d);
    __syncthreads();   // all warps done with s_warp (scan reuse)
    if (lane == 0) s_warp[wid] = acc;
    __syncthreads();
    if (wid == 0) {
        float a2 = s_warp[lane];
        #pragma unroll
        for (int d = 16; d >= 1; d >>= 1)
            a2 += __shfl_down_sync(FULLM, a2, d);
        if (lane == 0) atomicAdd(out, a2 * (1.0f / (float)BATCH));
    }
}

extern "C" void kernel_launch(void* const* d_in, const int* in_sizes, int n_in,
                              void* d_out, int out_size)
{
    const float* ranks  = (const float*)d_in[0];   // [B, C] f32
    const int*   labels = (const int*)d_in[1];     // [B, C] i32
    const void*  ids    = d_in[2];                 // [L] i64 or i32 (sniffed)
    float* out = (float*)d_out;                    // [1] f32

    zero_out_kernel<<<1, 1>>>(out);
    ranking_loss_kernel<<<BATCH, NT>>>(ranks, labels, ids, out);
}